// round 3
// baseline (speedup 1.0000x reference)
#include <cuda_runtime.h>

// Resample (upfirdn2d, FIR=[1,3,3,1], up=2)
// x: (4,256,128,128) f32 -> out: (4,256,256,256) f32
//
// Separable decomposition:
//   out row 2m   = 1*x[m-1] + 3*x[m]
//   out row 2m+1 = 3*x[m]   + 1*x[m+1]
//   out col 2n   = 1*x[n-2] + 3*x[n-1]
//   out col 2n+1 = 3*x[n-1] + 1*x[n]
//   scale 1/16; out-of-range input -> 0.
//
// R2 (resubmit after infra failure): 4 input rows per thread. 6 row-segments
// (2 float2 each) for 8 output rows -> 0.375 LDG / output pixel, front-batched.
// Interior rows loaded unconditionally (m0 in {0,4,...,124} guarantees
// m0..m0+3 valid); only the top/bottom halo rows are predicated.

#define H_IN  128
#define W_IN  128
#define W_OUT 256
#define BC    (4 * 256)
#define ROWS  4

__global__ __launch_bounds__(256) void upfir_up2_kernel(const float* __restrict__ x,
                                                        float* __restrict__ out) {
    const int t  = threadIdx.x;                                    // 0..63: input col pair (2t, 2t+1)
    const int m0 = (blockIdx.y * blockDim.y + threadIdx.y) * ROWS; // first input row of this thread
    const int bc = blockIdx.z;

    const float* __restrict__ xin = x + (size_t)bc * (H_IN * W_IN);
    float4* __restrict__ op       = (float4*)(out + (size_t)bc * (2 * H_IN) * W_OUT);

    const bool loOk = (t >= 1);

    // Rows m0-1 .. m0+ROWS at indices 0..ROWS+1.
    float2 lo[ROWS + 2], hi[ROWS + 2];

    // Interior rows: unconditional, front-batched.
#pragma unroll
    for (int i = 1; i <= ROWS; i++) {
        const float2* row = (const float2*)(xin + (size_t)(m0 - 1 + i) * W_IN);
        lo[i] = loOk ? __ldg(&row[t - 1]) : make_float2(0.f, 0.f);
        hi[i] = __ldg(&row[t]);
    }
    // Halo rows (predicated only at the image border).
    lo[0] = make_float2(0.f, 0.f); hi[0] = make_float2(0.f, 0.f);
    lo[ROWS + 1] = make_float2(0.f, 0.f); hi[ROWS + 1] = make_float2(0.f, 0.f);
    if (m0 > 0) {
        const float2* row = (const float2*)(xin + (size_t)(m0 - 1) * W_IN);
        if (loOk) lo[0] = __ldg(&row[t - 1]);
        hi[0] = __ldg(&row[t]);
    }
    if (m0 + ROWS < H_IN) {
        const float2* row = (const float2*)(xin + (size_t)(m0 + ROWS) * W_IN);
        if (loOk) lo[ROWS + 1] = __ldg(&row[t - 1]);
        hi[ROWS + 1] = __ldg(&row[t]);
    }

    const float s = 1.f / 16.f;
#pragma unroll
    for (int i = 0; i < ROWS; i++) {
        // input row m = m0 + i at index i+1
        const float e0 = lo[i].x + 3.f * lo[i + 1].x;
        const float e1 = lo[i].y + 3.f * lo[i + 1].y;
        const float e2 = hi[i].x + 3.f * hi[i + 1].x;
        const float e3 = hi[i].y + 3.f * hi[i + 1].y;

        const float d0 = 3.f * lo[i + 1].x + lo[i + 2].x;
        const float d1 = 3.f * lo[i + 1].y + lo[i + 2].y;
        const float d2 = 3.f * hi[i + 1].x + hi[i + 2].x;
        const float d3 = 3.f * hi[i + 1].y + hi[i + 2].y;

        float4 ve = make_float4((e0 + 3.f * e1) * s,
                                (3.f * e1 + e2) * s,
                                (e1 + 3.f * e2) * s,
                                (3.f * e2 + e3) * s);
        float4 vd = make_float4((d0 + 3.f * d1) * s,
                                (3.f * d1 + d2) * s,
                                (d1 + 3.f * d2) * s,
                                (3.f * d2 + d3) * s);

        const int m = m0 + i;
        op[(size_t)(2 * m) * (W_OUT / 4) + t]     = ve;   // coalesced 512B/warp STG.128
        op[(size_t)(2 * m + 1) * (W_OUT / 4) + t] = vd;
    }
}

extern "C" void kernel_launch(void* const* d_in, const int* in_sizes, int n_in,
                              void* d_out, int out_size) {
    const float* x = (const float*)d_in[0];
    float* out = (float*)d_out;

    dim3 block(64, 4, 1);                    // 256 threads: 64 col-pairs x 4 row-groups
    dim3 grid(1, H_IN / (4 * ROWS), BC);     // (1, 8, 1024)
    upfir_up2_kernel<<<grid, block>>>(x, out);
}

// round 5
// speedup vs baseline: 1.0281x; 1.0281x over previous
#include <cuda_runtime.h>

// Resample (upfirdn2d, FIR=[1,3,3,1], up=2)
// x: (4,256,128,128) f32 -> out: (4,256,256,256) f32
//
//   out row 2m   = 1*x[m-1] + 3*x[m]
//   out row 2m+1 = 3*x[m]   + 1*x[m+1]
//   out col 2n   = 1*x[n-2] + 3*x[n-1]
//   out col 2n+1 = 3*x[n-1] + 1*x[n]
//   scale 1/16; out-of-range -> 0.
//
// R4 resubmit (infra failure last round): one warp spans a full 128-col input
// row as two 64-col halves. Each lane loads ONLY its own float2 per row;
// left halo comes from lane-1 via __shfl_up of the vertical FIR results.
// No duplicate loads, no per-load predicates.

#define H_IN  128
#define W_IN  128
#define W_OUT 256
#define BC    (4 * 256)
#define ROWS  4

__device__ __forceinline__ float2 prev_lane_or_zero(float2 v, int lane) {
    float2 p;
    p.x = __shfl_up_sync(0xffffffffu, v.x, 1);
    p.y = __shfl_up_sync(0xffffffffu, v.y, 1);
    if (lane == 0) { p.x = 0.f; p.y = 0.f; }
    return p;
}

__device__ __forceinline__ float2 prev_lane_or_wrap(float2 v, float2 wrapSrc, int lane) {
    float2 p;
    p.x = __shfl_up_sync(0xffffffffu, v.x, 1);
    p.y = __shfl_up_sync(0xffffffffu, v.y, 1);
    const float wx = __shfl_sync(0xffffffffu, wrapSrc.x, 31);
    const float wy = __shfl_sync(0xffffffffu, wrapSrc.y, 31);
    if (lane == 0) { p.x = wx; p.y = wy; }
    return p;
}

__global__ __launch_bounds__(256) void upfir_up2_kernel(const float* __restrict__ x,
                                                        float* __restrict__ out) {
    const int lane = threadIdx.x;                                    // 0..31
    const int m0   = (blockIdx.y * blockDim.y + threadIdx.y) * ROWS; // 0,4,...,124
    const int bc   = blockIdx.z;

    const float2* __restrict__ xin = (const float2*)(x + (size_t)bc * (H_IN * W_IN));
    float* __restrict__ o          = out + (size_t)bc * (2 * H_IN) * W_OUT;

    // Rows m0-1 .. m0+ROWS at indices 0..ROWS+1; two halves per row.
    float2 a[ROWS + 2], b[ROWS + 2];

    // Interior rows m0..m0+ROWS-1: unconditional, front-batched.
#pragma unroll
    for (int i = 1; i <= ROWS; i++) {
        const float2* row = xin + (size_t)(m0 - 1 + i) * (W_IN / 2);
        a[i] = __ldg(row + lane);        // cols 2t, 2t+1
        b[i] = __ldg(row + 32 + lane);   // cols 64+2t, 65+2t
    }
    // Halo rows.
    a[0] = make_float2(0.f, 0.f); b[0] = a[0];
    a[ROWS + 1] = a[0];           b[ROWS + 1] = a[0];
    if (m0 > 0) {
        const float2* row = xin + (size_t)(m0 - 1) * (W_IN / 2);
        a[0] = __ldg(row + lane);
        b[0] = __ldg(row + 32 + lane);
    }
    if (m0 + ROWS < H_IN) {
        const float2* row = xin + (size_t)(m0 + ROWS) * (W_IN / 2);
        a[ROWS + 1] = __ldg(row + lane);
        b[ROWS + 1] = __ldg(row + 32 + lane);
    }

    const float s = 1.f / 16.f;
#pragma unroll
    for (int i = 0; i < ROWS; i++) {
        // Vertical FIR on own columns.
        float2 eA, dA, eB, dB;
        eA.x = a[i].x + 3.f * a[i + 1].x;     eA.y = a[i].y + 3.f * a[i + 1].y;
        dA.x = 3.f * a[i + 1].x + a[i + 2].x; dA.y = 3.f * a[i + 1].y + a[i + 2].y;
        eB.x = b[i].x + 3.f * b[i + 1].x;     eB.y = b[i].y + 3.f * b[i + 1].y;
        dB.x = 3.f * b[i + 1].x + b[i + 2].x; dB.y = 3.f * b[i + 1].y + b[i + 2].y;

        // Left halo (vertical results at cols 2t-2, 2t-1) from lane-1.
        const float2 peA = prev_lane_or_zero(eA, lane);
        const float2 pdA = prev_lane_or_zero(dA, lane);
        const float2 peB = prev_lane_or_wrap(eB, eA, lane);  // halfB lane0 <- halfA lane31 (cols 62,63)
        const float2 pdB = prev_lane_or_wrap(dB, dA, lane);

        // Horizontal FIR -> 4 output cols per half per row.
        float4 oEA = make_float4((peA.x + 3.f * peA.y) * s, (3.f * peA.y + eA.x) * s,
                                 (peA.y + 3.f * eA.x) * s,  (3.f * eA.x + eA.y) * s);
        float4 oDA = make_float4((pdA.x + 3.f * pdA.y) * s, (3.f * pdA.y + dA.x) * s,
                                 (pdA.y + 3.f * dA.x) * s,  (3.f * dA.x + dA.y) * s);
        float4 oEB = make_float4((peB.x + 3.f * peB.y) * s, (3.f * peB.y + eB.x) * s,
                                 (peB.y + 3.f * eB.x) * s,  (3.f * eB.x + eB.y) * s);
        float4 oDB = make_float4((pdB.x + 3.f * pdB.y) * s, (3.f * pdB.y + dB.x) * s,
                                 (pdB.y + 3.f * dB.x) * s,  (3.f * dB.x + dB.y) * s);

        const int m = m0 + i;
        float4* re = (float4*)(o + (size_t)(2 * m) * W_OUT);
        float4* rd = (float4*)(o + (size_t)(2 * m + 1) * W_OUT);
        __stcs(re + lane, oEA);        // 512B contiguous per warp
        __stcs(re + 32 + lane, oEB);
        __stcs(rd + lane, oDA);
        __stcs(rd + 32 + lane, oDB);
    }
}

extern "C" void kernel_launch(void* const* d_in, const int* in_sizes, int n_in,
                              void* d_out, int out_size) {
    const float* x = (const float*)d_in[0];
    float* out = (float*)d_out;

    dim3 block(32, 8, 1);                       // 256 threads: 1 warp x 8 row-groups
    dim3 grid(1, H_IN / (8 * ROWS), BC);        // (1, 4, 1024)
    upfir_up2_kernel<<<grid, block>>>(x, out);
}